// round 1
// baseline (speedup 1.0000x reference)
#include <cuda_runtime.h>
#include <cstdint>

// Problem constants (from reference: B=16, H=8, R=400, F=256, 2^k=8)
#define BH   128          // B*H
#define RDIM 400
#define FDIM 256
#define NROWS (BH * RDIM) // 51200

// Scratch for agg = masked_A @ feats  : [BH*R, F] floats = 52.4 MB
__device__ float g_agg[(size_t)NROWS * FDIM];

// ---------------------------------------------------------------------------
// Kernel 1: per (bh, i) row — compute ranks of columns {0,8,9,10,11,12},
// build the ≤7 kept positions, gather-accumulate agg[i,:] = sum val_k * feats[p_k,:]
// ---------------------------------------------------------------------------
__global__ __launch_bounds__(256) void mask_agg_kernel(
    const float* __restrict__ A,
    const float* __restrict__ feats,
    float* __restrict__ agg)
{
    const int row = blockIdx.x;          // 0..NROWS-1
    const int bh  = row / RDIM;
    const int i   = row - bh * RDIM;
    const int t   = threadIdx.x;

    __shared__ float s[RDIM];
    __shared__ int   cnt[6];
    __shared__ int   pos[7];
    __shared__ float pv[7];
    __shared__ int   npos;

    const float* arow = A + (size_t)row * RDIM;
    for (int j = t; j < RDIM; j += 256) s[j] = arow[j];
    if (t < 6) cnt[t] = 0;
    __syncthreads();

    // columns of interest: 0, 8..12
    const int cols[6] = {0, 8, 9, 10, 11, 12};
    float v0 = s[0], v1 = s[8], v2 = s[9], v3 = s[10], v4 = s[11], v5 = s[12];

    int loc0 = 0, loc1 = 0, loc2 = 0, loc3 = 0, loc4 = 0, loc5 = 0;
    for (int j = t; j < RDIM; j += 256) {
        float aj = s[j];
        // rank(c) = #(a_j > a_c) + #(j<c && a_j == a_c)   (stable descending sort)
        loc0 += (aj > v0) || (aj == v0 && j < 0);
        loc1 += (aj > v1) || (aj == v1 && j < 8);
        loc2 += (aj > v2) || (aj == v2 && j < 9);
        loc3 += (aj > v3) || (aj == v3 && j < 10);
        loc4 += (aj > v4) || (aj == v4 && j < 11);
        loc5 += (aj > v5) || (aj == v5 && j < 12);
    }
    // warp-reduce then shared-atomic (cheap: 6 atomics/thread worst case)
    atomicAdd(&cnt[0], loc0);
    atomicAdd(&cnt[1], loc1);
    atomicAdd(&cnt[2], loc2);
    atomicAdd(&cnt[3], loc3);
    atomicAdd(&cnt[4], loc4);
    atomicAdd(&cnt[5], loc5);
    __syncthreads();

    if (t == 0) {
        int n = 0;
        bool hasDiag = false;
        #pragma unroll
        for (int k = 0; k < 6; k++) {
            int p = cnt[k];           // rank of column cols[k]; all distinct
            pos[n] = p;
            pv[n]  = s[p];
            if (p == i) hasDiag = true;
            n++;
        }
        (void)cols;
        if (!hasDiag) { pos[n] = i; pv[n] = s[i]; n++; }
        npos = n;
    }
    __syncthreads();

    const int n = npos;
    const float* fbase = feats + (size_t)bh * RDIM * FDIM;
    float* aout = agg + (size_t)row * FDIM;

    // 256 threads -> one feature each
    {
        float acc = 0.f;
        #pragma unroll 7
        for (int m = 0; m < n; m++) {
            acc += pv[m] * __ldg(&fbase[(size_t)pos[m] * FDIM + t]);
        }
        aout[t] = acc;
    }
}

// ---------------------------------------------------------------------------
// Kernel 2: out = relu(agg @ W^T + b) + feats
// M = NROWS, N = FDIM, K = FDIM. W is [N,K] row-major (torch Linear weight).
// Tiled fp32 SGEMM: BM=64, BN=64, BK=16, 256 threads, 4x4 per thread.
// ---------------------------------------------------------------------------
#define BM 64
#define BN 64
#define BK 16

__global__ __launch_bounds__(256) void gemm_epilogue_kernel(
    const float* __restrict__ agg,
    const float* __restrict__ W,     // [FDIM, FDIM] row-major: W[f,k]
    const float* __restrict__ bias,  // [FDIM]
    const float* __restrict__ feats,
    float* __restrict__ out)
{
    __shared__ float As[BK][BM];   // As[kk][mm]
    __shared__ float Bs[BK][BN];   // Bs[kk][nn]

    const int m0 = blockIdx.x * BM;
    const int n0 = blockIdx.y * BN;
    const int t  = threadIdx.x;
    const int tx = t & 15;         // 0..15 -> n
    const int ty = t >> 4;         // 0..15 -> m

    float acc[4][4];
    #pragma unroll
    for (int r = 0; r < 4; r++)
        #pragma unroll
        for (int c = 0; c < 4; c++) acc[r][c] = 0.f;

    for (int k0 = 0; k0 < FDIM; k0 += BK) {
        // load A tile: 64x16 = 1024 elems, 256 threads -> 4 each
        #pragma unroll
        for (int u = 0; u < 4; u++) {
            int idx = t + u * 256;
            int mm = idx >> 4;        // /16
            int kk = idx & 15;
            As[kk][mm] = agg[(size_t)(m0 + mm) * FDIM + (k0 + kk)];
        }
        // load B tile (W[n,k]): 64x16
        #pragma unroll
        for (int u = 0; u < 4; u++) {
            int idx = t + u * 256;
            int nn = idx >> 4;
            int kk = idx & 15;
            Bs[kk][nn] = W[(size_t)(n0 + nn) * FDIM + (k0 + kk)];
        }
        __syncthreads();

        #pragma unroll
        for (int kk = 0; kk < BK; kk++) {
            float4 a4 = *reinterpret_cast<const float4*>(&As[kk][ty * 4]);
            float4 b4 = *reinterpret_cast<const float4*>(&Bs[kk][tx * 4]);
            float a[4] = {a4.x, a4.y, a4.z, a4.w};
            float b[4] = {b4.x, b4.y, b4.z, b4.w};
            #pragma unroll
            for (int r = 0; r < 4; r++)
                #pragma unroll
                for (int c = 0; c < 4; c++)
                    acc[r][c] += a[r] * b[c];
        }
        __syncthreads();
    }

    // epilogue: relu(acc + b[n]) + feats[m,n]
    #pragma unroll
    for (int r = 0; r < 4; r++) {
        int m = m0 + ty * 4 + r;
        #pragma unroll
        for (int c = 0; c < 4; c++) {
            int nn = n0 + tx * 4 + c;
            float v = acc[r][c] + __ldg(&bias[nn]);
            v = v > 0.f ? v : 0.f;
            size_t o = (size_t)m * FDIM + nn;
            out[o] = v + feats[o];
        }
    }
}

// ---------------------------------------------------------------------------
extern "C" void kernel_launch(void* const* d_in, const int* in_sizes, int n_in,
                              void* d_out, int out_size)
{
    const float* A     = (const float*)d_in[0];  // [16,8,400,400]
    const float* feats = (const float*)d_in[1];  // [16,8,400,256]
    const float* W     = (const float*)d_in[2];  // [256,256]
    const float* bias  = (const float*)d_in[3];  // [256]
    float* out = (float*)d_out;

    float* agg;
    cudaGetSymbolAddress((void**)&agg, g_agg);

    mask_agg_kernel<<<NROWS, 256>>>(A, feats, agg);

    dim3 grid(NROWS / BM, FDIM / BN);
    gemm_epilogue_kernel<<<grid, 256>>>(agg, W, bias, feats, out);
}

// round 6
// speedup vs baseline: 2.7709x; 2.7709x over previous
#include <cuda_runtime.h>
#include <cstdint>

// Problem constants: B=16, H=8, R=400, F=256, dilated 2^k = 8
#define BH    128
#define RDIM  400
#define FDIM  256
#define NROWS (BH * RDIM)   // 51200

// Scratch: agg (tf32-rounded fp32 bits) [NROWS, FDIM] = 52.4 MB, W tf32 copy
__device__ float g_agg[(size_t)NROWS * FDIM];
__device__ float g_Wt[FDIM * FDIM];

// ---------------------------------------------------------------------------
// helpers
// ---------------------------------------------------------------------------
__device__ __forceinline__ uint32_t smem_u32(const void* p) {
    uint32_t a;
    asm("{ .reg .u64 t; cvta.to.shared.u64 t, %1; cvt.u32.u64 %0, t; }"
        : "=r"(a) : "l"(p));
    return a;
}

__device__ __forceinline__ float f2tf32(float x) {
    uint32_t r;
    asm("cvt.rna.tf32.f32 %0, %1;" : "=r"(r) : "f"(x));
    return __uint_as_float(r);
}

__device__ __forceinline__ void ldsm_x4(uint32_t r[4], uint32_t addr) {
    asm volatile("ldmatrix.sync.aligned.m8n8.x4.shared.b16 {%0,%1,%2,%3}, [%4];"
                 : "=r"(r[0]), "=r"(r[1]), "=r"(r[2]), "=r"(r[3]) : "r"(addr));
}

__device__ __forceinline__ void mma_tf32(float c[4], const uint32_t a[4],
                                         const uint32_t b0, const uint32_t b1) {
    asm volatile(
        "mma.sync.aligned.m16n8k8.row.col.f32.tf32.tf32.f32 "
        "{%0,%1,%2,%3}, {%4,%5,%6,%7}, {%8,%9}, {%0,%1,%2,%3};"
        : "+f"(c[0]), "+f"(c[1]), "+f"(c[2]), "+f"(c[3])
        : "r"(a[0]), "r"(a[1]), "r"(a[2]), "r"(a[3]), "r"(b0), "r"(b1));
}

__device__ __forceinline__ void cp_async16(uint32_t saddr, const void* gaddr) {
    asm volatile("cp.async.cg.shared.global [%0], [%1], 16;"
                 :: "r"(saddr), "l"(gaddr));
}
#define CP_COMMIT() asm volatile("cp.async.commit_group;")
#define CP_WAIT(N)  asm volatile("cp.async.wait_group %0;" :: "n"(N))

// ---------------------------------------------------------------------------
// Kernel 0: W -> tf32-rounded copy
// ---------------------------------------------------------------------------
__global__ void conv_w_kernel(const float* __restrict__ W, float* __restrict__ Wt)
{
    int i = blockIdx.x * 256 + threadIdx.x;
    Wt[i] = f2tf32(W[i]);
}

// ---------------------------------------------------------------------------
// Kernel 1: mask + sparse gather.
// Kept columns of row i = rank positions (descending stable sort) of columns
// {0,8,9,10,11,12}, plus the diagonal. agg[row,:] = sum val_m * feats[pos_m,:]
// Stored tf32-rounded (feeds tensor-core GEMM A operand).
// ---------------------------------------------------------------------------
__global__ __launch_bounds__(256) void mask_agg_kernel(
    const float* __restrict__ A,
    const float* __restrict__ feats,
    float* __restrict__ agg)
{
    const int row = blockIdx.x;
    const int bh  = row / RDIM;
    const int i   = row - bh * RDIM;
    const int t   = threadIdx.x;
    const int lid = t & 31;
    const int wid = t >> 5;

    __shared__ float s[RDIM];
    __shared__ int   poss[7];
    __shared__ float pvs[7];
    __shared__ int   npos_s;

    const float4* arow4 = reinterpret_cast<const float4*>(A + (size_t)row * RDIM);
    if (t < RDIM / 4) reinterpret_cast<float4*>(s)[t] = arow4[t];
    __syncthreads();

    if (wid < 6) {                       // 256 threads -> warps 0..5 valid
        const int colc = (wid == 0) ? 0 : (7 + wid);   // {0,8,9,10,11,12}
        const float v = s[colc];
        int cnt = 0;
        for (int j = lid; j < RDIM; j += 32) {
            float aj = s[j];
            cnt += (aj > v) || (aj == v && j < colc);  // stable descending rank
        }
        #pragma unroll
        for (int o = 16; o; o >>= 1) cnt += __shfl_down_sync(0xffffffffu, cnt, o);
        if (lid == 0) poss[wid] = cnt;
    }
    __syncthreads();

    if (t == 0) {
        int n = 6;
        bool diag = false;
        #pragma unroll
        for (int k = 0; k < 6; k++) {
            int p = poss[k];
            pvs[k] = s[p];
            if (p == i) diag = true;
        }
        if (!diag) { poss[6] = i; pvs[6] = s[i]; n = 7; }
        npos_s = n;
    }
    __syncthreads();

    const int n = npos_s;
    const float* fb = feats + (size_t)bh * RDIM * FDIM;
    float acc = 0.f;
    #pragma unroll
    for (int m = 0; m < 7; m++) {
        if (m < n) acc += pvs[m] * __ldg(&fb[(size_t)poss[m] * FDIM + t]);
    }
    agg[(size_t)row * FDIM + t] = f2tf32(acc);
}

// ---------------------------------------------------------------------------
// Kernel 2: out = relu(agg @ W^T + b) + feats via mma.sync tf32 (m16n8k8).
// CTA tile 128x128, BK=32, 8 warps in 4(M)x2(N), warp tile 32x64.
// cp.async double-buffered; smem row stride 36 floats (conflict-free ldmatrix).
// ---------------------------------------------------------------------------
#define MT 128
#define NT 128
#define BK 32
#define NCHUNK (FDIM / BK)      // 8
#define RS 36                   // smem row stride (floats): 144B, 16B-aligned
#define STAGE_FLOATS (2 * MT * RS)          // A + B per stage = 9216
#define SMEM_FLOATS  (2 * STAGE_FLOATS)     // 18432 floats = 73728 B
#define EPS 132                 // epilogue row stride (floats)

extern __shared__ float sm_dyn[];

__global__ __launch_bounds__(256, 2) void gemm_tf32_kernel(
    const float* __restrict__ agg,   // tf32 bits
    const float* __restrict__ Wt,    // tf32 bits, [N,K] row-major
    const float* __restrict__ bias,
    const float* __restrict__ feats,
    float* __restrict__ out)
{
    const int t   = threadIdx.x;
    const int wid = t >> 5;
    const int lid = t & 31;
    const int m0  = blockIdx.x * MT;
    const int n0  = blockIdx.y * NT;
    const int wm  = wid & 3;        // warp M index (0..3)
    const int wn  = wid >> 2;       // warp N index (0..1)

    const uint32_t sb = smem_u32(sm_dyn);

    // cp.async source/dest precompute: 8 x 16B per thread per chunk
    // e in [0,2048): first 1024 -> A tile, rest -> B tile.
    // ldmatrix per-lane base addresses (byte):
    //   A frag: row = wm*32 + ((lid>>3)&1)*8 + (lid&7), col4 = (lid>>4)*4
    const uint32_t aAddrBase = sb +
        ((uint32_t)((wm * 32 + ((lid >> 3) & 1) * 8 + (lid & 7)) * RS
                    + (lid >> 4) * 4) << 2);
    //   B frag: row(n) = wn*64 + (lid>>4)*8 + (lid&7), col4 = ((lid>>3)&1)*4
    const uint32_t bAddrBase = sb + (uint32_t)(MT * RS * 4) +
        ((uint32_t)((wn * 64 + (lid >> 4) * 8 + (lid & 7)) * RS
                    + ((lid >> 3) & 1) * 4) << 2);

    float acc[2][8][4];
    #pragma unroll
    for (int a = 0; a < 2; a++)
        #pragma unroll
        for (int j = 0; j < 8; j++)
            #pragma unroll
            for (int k = 0; k < 4; k++) acc[a][j][k] = 0.f;

    auto issue_chunk = [&](int c, int stage) {
        const uint32_t sbase = sb + (uint32_t)(stage * STAGE_FLOATS * 4);
        #pragma unroll
        for (int u = 0; u < 8; u++) {
            int idx = u * 256 + t;          // 0..2047
            int e   = idx & 1023;
            int r   = e >> 3;
            int c4  = e & 7;
            uint32_t sd;
            const float* gs;
            if (idx < 1024) {
                sd = sbase + (uint32_t)((r * RS + c4 * 4) << 2);
                gs = agg + (size_t)(m0 + r) * FDIM + c * BK + c4 * 4;
            } else {
                sd = sbase + (uint32_t)(MT * RS * 4) + (uint32_t)((r * RS + c4 * 4) << 2);
                gs = Wt + (size_t)(n0 + r) * FDIM + c * BK + c4 * 4;
            }
            cp_async16(sd, gs);
        }
        CP_COMMIT();
    };

    issue_chunk(0, 0);

    for (int c = 0; c < NCHUNK; c++) {
        const int stage = c & 1;
        if (c + 1 < NCHUNK) {
            issue_chunk(c + 1, (c + 1) & 1);
            CP_WAIT(1);
        } else {
            CP_WAIT(0);
        }
        __syncthreads();

        const uint32_t aS = aAddrBase + (uint32_t)(stage * STAGE_FLOATS * 4);
        const uint32_t bS = bAddrBase + (uint32_t)(stage * STAGE_FLOATS * 4);

        #pragma unroll
        for (int ks = 0; ks < 4; ks++) {
            uint32_t afr[2][4];
            #pragma unroll
            for (int tm = 0; tm < 2; tm++)
                ldsm_x4(afr[tm], aS + (uint32_t)((tm * 16 * RS + ks * 8) << 2));

            uint32_t bfr[4][4];   // bfr[jj] = {b0(2jj), b1(2jj), b0(2jj+1), b1(2jj+1)}
            #pragma unroll
            for (int jj = 0; jj < 4; jj++)
                ldsm_x4(bfr[jj], bS + (uint32_t)((jj * 16 * RS + ks * 8) << 2));

            #pragma unroll
            for (int tm = 0; tm < 2; tm++)
                #pragma unroll
                for (int j = 0; j < 8; j++)
                    mma_tf32(acc[tm][j], afr[tm], bfr[j >> 1][(j & 1) * 2],
                             bfr[j >> 1][(j & 1) * 2 + 1]);
        }
        __syncthreads();
    }

    // ---- epilogue: stage accumulators to smem, then coalesced store ----
    {
        float* ep = sm_dyn;
        #pragma unroll
        for (int tm = 0; tm < 2; tm++) {
            int rbase = wm * 32 + tm * 16 + (lid >> 2);
            int cbase = wn * 64 + (lid & 3) * 2;
            #pragma unroll
            for (int j = 0; j < 8; j++) {
                float2 lo = make_float2(acc[tm][j][0], acc[tm][j][1]);
                float2 hi = make_float2(acc[tm][j][2], acc[tm][j][3]);
                *reinterpret_cast<float2*>(&ep[rbase * EPS + cbase + j * 8])       = lo;
                *reinterpret_cast<float2*>(&ep[(rbase + 8) * EPS + cbase + j * 8]) = hi;
            }
        }
        __syncthreads();

        const float4* f4 = reinterpret_cast<const float4*>(feats);
        float4* o4 = reinterpret_cast<float4*>(out);
        const float4* b4 = reinterpret_cast<const float4*>(bias);
        #pragma unroll
        for (int it = 0; it < 16; it++) {
            int lin = it * 256 + t;
            int r   = lin >> 5;          // 0..127
            int c4  = lin & 31;          // 0..31 float4s
            float4 v = *reinterpret_cast<const float4*>(&ep[r * EPS + c4 * 4]);
            float4 bb = __ldg(&b4[(n0 >> 2) + c4]);
            size_t gi = ((size_t)(m0 + r) * FDIM + n0) / 4 + c4;
            float4 ff = __ldg(&f4[gi]);
            v.x = fmaxf(v.x + bb.x, 0.f) + ff.x;
            v.y = fmaxf(v.y + bb.y, 0.f) + ff.y;
            v.z = fmaxf(v.z + bb.z, 0.f) + ff.z;
            v.w = fmaxf(v.w + bb.w, 0.f) + ff.w;
            o4[gi] = v;
        }
    }
}

// ---------------------------------------------------------------------------
extern "C" void kernel_launch(void* const* d_in, const int* in_sizes, int n_in,
                              void* d_out, int out_size)
{
    const float* A     = (const float*)d_in[0];  // [16,8,400,400]
    const float* feats = (const float*)d_in[1];  // [16,8,400,256]
    const float* W     = (const float*)d_in[2];  // [256,256]
    const float* bias  = (const float*)d_in[3];  // [256]
    float* out = (float*)d_out;

    float* agg;  cudaGetSymbolAddress((void**)&agg, g_agg);
    float* Wt;   cudaGetSymbolAddress((void**)&Wt,  g_Wt);

    static bool attr_set = false;
    if (!attr_set) {
        cudaFuncSetAttribute(gemm_tf32_kernel,
                             cudaFuncAttributeMaxDynamicSharedMemorySize,
                             SMEM_FLOATS * 4);
        attr_set = true;
    }

    conv_w_kernel<<<FDIM * FDIM / 256, 256>>>(W, Wt);
    mask_agg_kernel<<<NROWS, 256>>>(A, feats, agg);

    dim3 grid(NROWS / MT, FDIM / NT);   // (400, 2)
    gemm_tf32_kernel<<<grid, 256, SMEM_FLOATS * 4>>>(agg, Wt, bias, feats, out);
}